// round 6
// baseline (speedup 1.0000x reference)
#include <cuda_runtime.h>
#include <cuda_fp16.h>

#define BATCH 16
#define NMAT  1024
#define DDIM  256
#define ITERS 101          // 100 scan steps + 1 final sinkhorn_step
#define CLUSTER 8
#define GRID_SINK (BATCH * CLUSTER)      // 128 blocks = 16 independent clusters
#define ROWS_PER_BLK 128
#define TPB_SINK  512                    // 16 warps

typedef unsigned long long ull;

// ---------------- f32x2 helpers (FFMA2 — only reachable via PTX) ----------------
__device__ __forceinline__ void ffma2(ull& d, ull a, ull b) {
    asm("fma.rn.f32x2 %0, %1, %2, %3;" : "=l"(d) : "l"(a), "l"(b), "l"(d));
}
__device__ __forceinline__ ull packf2(float lo, float hi) {
    ull r; asm("mov.b64 %0, {%1, %2};" : "=l"(r) : "f"(lo), "f"(hi)); return r;
}
__device__ __forceinline__ float2 unpackf2(ull v) {
    float lo, hi; asm("mov.b64 {%0, %1}, %2;" : "=f"(lo), "=f"(hi) : "l"(v));
    return make_float2(lo, hi);
}

// ---------------- DSMEM / cluster helpers ----------------
__device__ __forceinline__ unsigned smem_u32(const void* p) {
    return (unsigned)__cvta_generic_to_shared(p);
}
__device__ __forceinline__ unsigned mapa_rank(unsigned addr, int rank) {
    unsigned r;
    asm("mapa.shared::cluster.u32 %0, %1, %2;" : "=r"(r) : "r"(addr), "r"(rank));
    return r;
}
__device__ __forceinline__ void st_cluster_f32(unsigned addr, float v) {
    asm volatile("st.shared::cluster.f32 [%0], %1;" :: "r"(addr), "f"(v) : "memory");
}
__device__ __forceinline__ void cluster_sync() {
    asm volatile("barrier.cluster.arrive.aligned;" ::: "memory");
    asm volatile("barrier.cluster.wait.aligned;" ::: "memory");
}

// ---------------- device scratch (no allocations allowed) ----------------
__device__ float  g_nA[BATCH * NMAT * DDIM];                 // 16.8 MB
__device__ float  g_nB[BATCH * NMAT * DDIM];                 // 16.8 MB
__device__ __half g_K[(size_t)BATCH * NMAT * NMAT];          // 33.5 MB (L2-resident)

// ---------------- l2 normalize: warp per row (256 elems) ----------------
__global__ void norm_kernel(const float* __restrict__ in, int which) {
    int w = threadIdx.x >> 5, lane = threadIdx.x & 31;
    int row = blockIdx.x * 8 + w;                      // 2048 blocks * 8 = 16384 rows
    const float4* src = reinterpret_cast<const float4*>(in) + (size_t)row * 64;
    float4 x0 = src[lane];
    float4 x1 = src[lane + 32];
    float s = x0.x * x0.x + x0.y * x0.y + x0.z * x0.z + x0.w * x0.w
            + x1.x * x1.x + x1.y * x1.y + x1.z * x1.z + x1.w * x1.w;
    #pragma unroll
    for (int off = 16; off; off >>= 1) s += __shfl_xor_sync(0xffffffffu, s, off);
    float r = rsqrtf(fmaxf(s, 1e-12f));
    float* dst = (which ? g_nB : g_nA) + (size_t)row * 256;
    reinterpret_cast<float4*>(dst)[lane]      = make_float4(x0.x*r, x0.y*r, x0.z*r, x0.w*r);
    reinterpret_cast<float4*>(dst)[lane + 32] = make_float4(x1.x*r, x1.y*r, x1.z*r, x1.w*r);
}

// ---------------- GEMM (plain FFMA): S = nA*nB^T, K = fp16(exp(5*clamp(S))) ----
// grid (8, 8, 16), block 256, 128x128 tile, 8x8 per thread, BK=32
__global__ void __launch_bounds__(256) gemm_expk_kernel(float* __restrict__ Sout) {
    __shared__ float As[32 * 128];   // [k][i]
    __shared__ float Bs[32 * 128];   // [k][j]
    const int b  = blockIdx.z;
    const int i0 = blockIdx.y * 128;
    const int j0 = blockIdx.x * 128;
    const float* Ag = g_nA + (size_t)b * NMAT * DDIM;
    const float* Bg = g_nB + (size_t)b * NMAT * DDIM;
    const int tid = threadIdx.x;
    const int tx = tid & 15, ty = tid >> 4;
    const int lr = tid >> 3;
    const int lc = tid & 7;

    float acc[8][8];
    #pragma unroll
    for (int i = 0; i < 8; i++)
        #pragma unroll
        for (int j = 0; j < 8; j++) acc[i][j] = 0.f;

    for (int kc = 0; kc < 8; kc++) {
        __syncthreads();
        #pragma unroll
        for (int g = 0; g < 4; g++) {
            int row = lr + 32 * g;
            float4 av = *reinterpret_cast<const float4*>(
                &Ag[(size_t)(i0 + row) * DDIM + kc * 32 + lc * 4]);
            As[(lc * 4 + 0) * 128 + row] = av.x;
            As[(lc * 4 + 1) * 128 + row] = av.y;
            As[(lc * 4 + 2) * 128 + row] = av.z;
            As[(lc * 4 + 3) * 128 + row] = av.w;
            float4 bv = *reinterpret_cast<const float4*>(
                &Bg[(size_t)(j0 + row) * DDIM + kc * 32 + lc * 4]);
            Bs[(lc * 4 + 0) * 128 + row] = bv.x;
            Bs[(lc * 4 + 1) * 128 + row] = bv.y;
            Bs[(lc * 4 + 2) * 128 + row] = bv.z;
            Bs[(lc * 4 + 3) * 128 + row] = bv.w;
        }
        __syncthreads();
        #pragma unroll
        for (int k = 0; k < 32; k++) {
            float4 a0 = *reinterpret_cast<const float4*>(&As[k * 128 + ty * 8]);
            float4 a1 = *reinterpret_cast<const float4*>(&As[k * 128 + ty * 8 + 4]);
            float4 b0 = *reinterpret_cast<const float4*>(&Bs[k * 128 + tx * 8]);
            float4 b1 = *reinterpret_cast<const float4*>(&Bs[k * 128 + tx * 8 + 4]);
            float a[8] = {a0.x, a0.y, a0.z, a0.w, a1.x, a1.y, a1.z, a1.w};
            float bb[8] = {b0.x, b0.y, b0.z, b0.w, b1.x, b1.y, b1.z, b1.w};
            #pragma unroll
            for (int ii = 0; ii < 8; ii++)
                #pragma unroll
                for (int jj = 0; jj < 8; jj++)
                    acc[ii][jj] = fmaf(a[ii], bb[jj], acc[ii][jj]);
        }
    }

    #pragma unroll
    for (int ii = 0; ii < 8; ii++) {
        int i = i0 + ty * 8 + ii;
        size_t base = ((size_t)b << 20) + (size_t)i * NMAT + j0 + tx * 8;
        *reinterpret_cast<float4*>(&Sout[base]) =
            make_float4(acc[ii][0], acc[ii][1], acc[ii][2], acc[ii][3]);
        *reinterpret_cast<float4*>(&Sout[base + 4]) =
            make_float4(acc[ii][4], acc[ii][5], acc[ii][6], acc[ii][7]);
        float e[8];
        #pragma unroll
        for (int jj = 0; jj < 8; jj++)
            e[jj] = __expf(5.f * fminf(fmaxf(acc[ii][jj], -3.f), 3.f));
        __half2 h0 = __floats2half2_rn(e[0], e[1]);
        __half2 h1 = __floats2half2_rn(e[2], e[3]);
        __half2 h2 = __floats2half2_rn(e[4], e[5]);
        __half2 h3 = __floats2half2_rn(e[6], e[7]);
        uint4 kq;
        kq.x = *reinterpret_cast<unsigned*>(&h0);
        kq.y = *reinterpret_cast<unsigned*>(&h1);
        kq.z = *reinterpret_cast<unsigned*>(&h2);
        kq.w = *reinterpret_cast<unsigned*>(&h3);
        *reinterpret_cast<uint4*>(&g_K[base]) = kq;
    }
}

// ---------------- persistent Sinkhorn: one batch per 8-CTA cluster ----------------
// Block = (batch b = blockIdx.x/8, rank = blockIdx.x%8). 128 rows per block, 8 per warp.
// Cross-block exchange of column partials + v entirely via DSMEM + cluster barriers.
// smem layout (floats): v_s[1024] | u_s[128] | gather[128][8] | colpart[16][1024]
__global__ void __launch_bounds__(TPB_SINK, 1) __cluster_dims__(CLUSTER, 1, 1)
sinkhorn_kernel(float* __restrict__ Pout) {
    const int b    = blockIdx.x >> 3;
    const int rank = blockIdx.x & 7;
    const int row0 = rank * ROWS_PER_BLK;
    const int tid = threadIdx.x, w = tid >> 5, lane = tid & 31;

    extern __shared__ float sm[];
    float* v_s     = sm;            // 1024
    float* u_s     = sm + 1024;     // 128
    float* gather  = sm + 1152;     // [col_local][slot] : 128*8
    float* colpart = sm + 2176;     // 16 * 1024

    const unsigned gather_base = smem_u32(gather);
    const unsigned vs_base     = smem_u32(v_s);

    const __half* Kb = g_K + ((size_t)b << 20);

    ull vp[16];   // packed v pairs for owned columns
    ull ca[16];   // packed column accumulators

    for (int t = 0; t < ITERS; t++) {
        // ---- phase A: v into registers ----
        if (t == 0) {
            #pragma unroll
            for (int m = 0; m < 16; m++) vp[m] = packf2(1.0f, 1.0f);
        } else {
            #pragma unroll
            for (int k = 0; k < 4; k++) {
                ulonglong2 va = *reinterpret_cast<const ulonglong2*>(&v_s[256*k + 8*lane]);
                vp[4*k+0] = va.x;  vp[4*k+1] = va.y;
                ulonglong2 vb = *reinterpret_cast<const ulonglong2*>(&v_s[256*k + 8*lane + 4]);
                vp[4*k+2] = vb.x;  vp[4*k+3] = vb.y;
            }
        }
        #pragma unroll
        for (int m = 0; m < 16; m++) ca[m] = 0ull;

        // ---- phase B: fused row matvec + col accumulate (one K pass) ----
        #pragma unroll 2
        for (int rr = 0; rr < 8; rr++) {
            const int il = w + 16 * rr;
            const uint4* Krow = reinterpret_cast<const uint4*>(Kb + (size_t)(row0 + il) * NMAT);
            ull kf[16];
            ull d0 = 0ull, d1 = 0ull;
            #pragma unroll
            for (int k = 0; k < 4; k++) {
                uint4 q = Krow[32*k + lane];
                float2 f0 = __half22float2(*reinterpret_cast<__half2*>(&q.x));
                float2 f1 = __half22float2(*reinterpret_cast<__half2*>(&q.y));
                float2 f2 = __half22float2(*reinterpret_cast<__half2*>(&q.z));
                float2 f3 = __half22float2(*reinterpret_cast<__half2*>(&q.w));
                kf[4*k+0] = packf2(f0.x, f0.y);
                kf[4*k+1] = packf2(f1.x, f1.y);
                kf[4*k+2] = packf2(f2.x, f2.y);
                kf[4*k+3] = packf2(f3.x, f3.y);
                ffma2(d0, kf[4*k+0], vp[4*k+0]);
                ffma2(d1, kf[4*k+1], vp[4*k+1]);
                ffma2(d0, kf[4*k+2], vp[4*k+2]);
                ffma2(d1, kf[4*k+3], vp[4*k+3]);
            }
            float2 dd0 = unpackf2(d0), dd1 = unpackf2(d1);
            float dot = (dd0.x + dd0.y) + (dd1.x + dd1.y);
            #pragma unroll
            for (int off = 16; off; off >>= 1) dot += __shfl_xor_sync(0xffffffffu, dot, off);
            float u = 1.0f / dot;
            if (lane == 0) u_s[il] = u;
            ull up = packf2(u, u);
            #pragma unroll
            for (int m = 0; m < 16; m++) ffma2(ca[m], up, kf[m]);
        }

        // ---- phase C: warp partials -> block partial -> push to column owners ----
        #pragma unroll
        for (int k = 0; k < 4; k++) {
            float2 p0 = unpackf2(ca[4*k+0]);
            float2 p1 = unpackf2(ca[4*k+1]);
            float2 p2 = unpackf2(ca[4*k+2]);
            float2 p3 = unpackf2(ca[4*k+3]);
            *reinterpret_cast<float4*>(&colpart[w*1024 + 256*k + 8*lane]) =
                make_float4(p0.x, p0.y, p1.x, p1.y);
            *reinterpret_cast<float4*>(&colpart[w*1024 + 256*k + 8*lane + 4]) =
                make_float4(p2.x, p2.y, p3.x, p3.y);
        }
        __syncthreads();
        #pragma unroll
        for (int c = tid; c < NMAT; c += TPB_SINK) {   // 2 columns per thread
            float s = 0.f;
            #pragma unroll
            for (int ww = 0; ww < 16; ww++) s += colpart[ww * 1024 + c];
            const int owner = c >> 7;
            unsigned dst = mapa_rank(gather_base + (unsigned)(((c & 127) * 8 + rank) * 4), owner);
            st_cluster_f32(dst, s);
        }
        cluster_sync();                                 // gather complete cluster-wide

        // ---- owner reduces its 128 columns, broadcasts v chunk to all CTAs ----
        if (tid < 128) {
            float s = 0.f;
            #pragma unroll
            for (int p = 0; p < 8; p++) s += gather[tid * 8 + p];
            float v = 1.0f / s;
            unsigned vaddr = vs_base + (unsigned)((rank * 128 + tid) * 4);
            #pragma unroll
            for (int p = 0; p < 8; p++) st_cluster_f32(mapa_rank(vaddr, p), v);
        }
        cluster_sync();                                 // v_s complete everywhere
    }

    // ---- final: P_out = u * K * v (u_s from last iter, v_s from last exchange) ----
    {
        float vr[32];
        #pragma unroll
        for (int k = 0; k < 4; k++) {
            float4 va = *reinterpret_cast<const float4*>(&v_s[256*k + 8*lane]);
            float4 vb = *reinterpret_cast<const float4*>(&v_s[256*k + 8*lane + 4]);
            vr[8*k+0] = va.x; vr[8*k+1] = va.y; vr[8*k+2] = va.z; vr[8*k+3] = va.w;
            vr[8*k+4] = vb.x; vr[8*k+5] = vb.y; vr[8*k+6] = vb.z; vr[8*k+7] = vb.w;
        }
        #pragma unroll 2
        for (int rr = 0; rr < 8; rr++) {
            const int il = w + 16 * rr;
            const int i = row0 + il;
            const uint4* Krow = reinterpret_cast<const uint4*>(Kb + (size_t)i * NMAT);
            float u = u_s[il];
            float* Orow = Pout + ((size_t)b << 20) + (size_t)i * NMAT;
            #pragma unroll
            for (int k = 0; k < 4; k++) {
                uint4 q = Krow[32*k + lane];
                float2 f0 = __half22float2(*reinterpret_cast<__half2*>(&q.x));
                float2 f1 = __half22float2(*reinterpret_cast<__half2*>(&q.y));
                float2 f2 = __half22float2(*reinterpret_cast<__half2*>(&q.z));
                float2 f3 = __half22float2(*reinterpret_cast<__half2*>(&q.w));
                *reinterpret_cast<float4*>(&Orow[256*k + 8*lane]) =
                    make_float4(u*f0.x*vr[8*k+0], u*f0.y*vr[8*k+1],
                                u*f1.x*vr[8*k+2], u*f1.y*vr[8*k+3]);
                *reinterpret_cast<float4*>(&Orow[256*k + 8*lane + 4]) =
                    make_float4(u*f2.x*vr[8*k+4], u*f2.y*vr[8*k+5],
                                u*f3.x*vr[8*k+6], u*f3.y*vr[8*k+7]);
            }
        }
    }
}

// ---------------- launch ----------------
extern "C" void kernel_launch(void* const* d_in, const int* in_sizes, int n_in,
                              void* d_out, int out_size) {
    const float* fA = (const float*)d_in[0];
    const float* fB = (const float*)d_in[1];
    float* out  = (float*)d_out;
    float* Pout = out;                                        // P_out: [16,1024,1024]
    float* Sout = out + (size_t)BATCH * NMAT * NMAT;          // Sij:   [16,1024,1024]

    norm_kernel<<<2048, 256>>>(fA, 0);
    norm_kernel<<<2048, 256>>>(fB, 1);

    dim3 ggrid(8, 8, BATCH);
    gemm_expk_kernel<<<ggrid, 256>>>(Sout);

    const int smem_bytes = (1024 + 128 + 128 * 8 + 16 * 1024) * sizeof(float);  // 74240
    static int smem_set = 0;
    if (!smem_set) {
        cudaFuncSetAttribute(sinkhorn_kernel,
                             cudaFuncAttributeMaxDynamicSharedMemorySize, smem_bytes);
        smem_set = 1;
    }
    sinkhorn_kernel<<<GRID_SINK, TPB_SINK, smem_bytes>>>(Pout);
}

// round 7
// speedup vs baseline: 1.2718x; 1.2718x over previous
#include <cuda_runtime.h>
#include <cuda_fp16.h>

#define BATCH 16
#define NMAT  1024
#define DDIM  256
#define ITERS 101          // 100 scan steps + 1 final sinkhorn_step
#define NBLK_PER_B 8
#define GRID_SINK (BATCH * NBLK_PER_B)   // 128 blocks, 1 per SM (148 SMs)
#define ROWS_PER_BLK 128
#define TPB_SINK  512                    // 16 warps, 8 rows/warp, 4 pairs

typedef unsigned long long ull;

// ---------------- f32x2 helpers (FFMA2 — only reachable via PTX) ----------------
__device__ __forceinline__ void ffma2(ull& d, ull a, ull b) {
    asm("fma.rn.f32x2 %0, %1, %2, %3;" : "=l"(d) : "l"(a), "l"(b), "l"(d));
}
__device__ __forceinline__ ull packf2(float lo, float hi) {
    ull r; asm("mov.b64 %0, {%1, %2};" : "=l"(r) : "f"(lo), "f"(hi)); return r;
}
__device__ __forceinline__ float2 unpackf2(ull v) {
    float lo, hi; asm("mov.b64 {%0, %1}, %2;" : "=f"(lo), "=f"(hi) : "l"(v));
    return make_float2(lo, hi);
}
__device__ __forceinline__ ull h2f2(unsigned h) {   // half2 -> packed f32x2
    float2 f = __half22float2(*reinterpret_cast<__half2*>(&h));
    return packf2(f.x, f.y);
}

// ---------------- device scratch (no allocations allowed) ----------------
__device__ float  g_nA[BATCH * NMAT * DDIM];                 // 16.8 MB
__device__ float  g_nB[BATCH * NMAT * DDIM];                 // 16.8 MB
__device__ __half g_K[(size_t)BATCH * NMAT * NMAT];          // 33.5 MB (L2-resident)
__device__ float  g_part[2][BATCH][NBLK_PER_B][NMAT];        // double-buffered col partials
__device__ unsigned g_bar_count;
__device__ unsigned g_bar_gen;

// ---------------- l2 normalize: warp per row (256 elems) ----------------
__global__ void norm_kernel(const float* __restrict__ in, int which) {
    int w = threadIdx.x >> 5, lane = threadIdx.x & 31;
    int row = blockIdx.x * 8 + w;                      // 2048 blocks * 8 = 16384 rows
    const float4* src = reinterpret_cast<const float4*>(in) + (size_t)row * 64;
    float4 x0 = src[lane];
    float4 x1 = src[lane + 32];
    float s = x0.x * x0.x + x0.y * x0.y + x0.z * x0.z + x0.w * x0.w
            + x1.x * x1.x + x1.y * x1.y + x1.z * x1.z + x1.w * x1.w;
    #pragma unroll
    for (int off = 16; off; off >>= 1) s += __shfl_xor_sync(0xffffffffu, s, off);
    float r = rsqrtf(fmaxf(s, 1e-12f));
    float* dst = (which ? g_nB : g_nA) + (size_t)row * 256;
    reinterpret_cast<float4*>(dst)[lane]      = make_float4(x0.x*r, x0.y*r, x0.z*r, x0.w*r);
    reinterpret_cast<float4*>(dst)[lane + 32] = make_float4(x1.x*r, x1.y*r, x1.z*r, x1.w*r);
}

// ---------------- GEMM (plain FFMA, R1): S = nA*nB^T, K = fp16(exp(5*clamp(S))) ----
// grid (8, 8, 16), block 256, 128x128 tile, 8x8 per thread, BK=32
__global__ void __launch_bounds__(256) gemm_expk_kernel(float* __restrict__ Sout) {
    __shared__ float As[32 * 128];   // [k][i]
    __shared__ float Bs[32 * 128];   // [k][j]
    const int b  = blockIdx.z;
    const int i0 = blockIdx.y * 128;
    const int j0 = blockIdx.x * 128;
    const float* Ag = g_nA + (size_t)b * NMAT * DDIM;
    const float* Bg = g_nB + (size_t)b * NMAT * DDIM;
    const int tid = threadIdx.x;
    const int tx = tid & 15, ty = tid >> 4;
    const int lr = tid >> 3;
    const int lc = tid & 7;

    float acc[8][8];
    #pragma unroll
    for (int i = 0; i < 8; i++)
        #pragma unroll
        for (int j = 0; j < 8; j++) acc[i][j] = 0.f;

    for (int kc = 0; kc < 8; kc++) {
        __syncthreads();
        #pragma unroll
        for (int g = 0; g < 4; g++) {
            int row = lr + 32 * g;
            float4 av = *reinterpret_cast<const float4*>(
                &Ag[(size_t)(i0 + row) * DDIM + kc * 32 + lc * 4]);
            As[(lc * 4 + 0) * 128 + row] = av.x;
            As[(lc * 4 + 1) * 128 + row] = av.y;
            As[(lc * 4 + 2) * 128 + row] = av.z;
            As[(lc * 4 + 3) * 128 + row] = av.w;
            float4 bv = *reinterpret_cast<const float4*>(
                &Bg[(size_t)(j0 + row) * DDIM + kc * 32 + lc * 4]);
            Bs[(lc * 4 + 0) * 128 + row] = bv.x;
            Bs[(lc * 4 + 1) * 128 + row] = bv.y;
            Bs[(lc * 4 + 2) * 128 + row] = bv.z;
            Bs[(lc * 4 + 3) * 128 + row] = bv.w;
        }
        __syncthreads();
        #pragma unroll
        for (int k = 0; k < 32; k++) {
            float4 a0 = *reinterpret_cast<const float4*>(&As[k * 128 + ty * 8]);
            float4 a1 = *reinterpret_cast<const float4*>(&As[k * 128 + ty * 8 + 4]);
            float4 b0 = *reinterpret_cast<const float4*>(&Bs[k * 128 + tx * 8]);
            float4 b1 = *reinterpret_cast<const float4*>(&Bs[k * 128 + tx * 8 + 4]);
            float a[8] = {a0.x, a0.y, a0.z, a0.w, a1.x, a1.y, a1.z, a1.w};
            float bb[8] = {b0.x, b0.y, b0.z, b0.w, b1.x, b1.y, b1.z, b1.w};
            #pragma unroll
            for (int ii = 0; ii < 8; ii++)
                #pragma unroll
                for (int jj = 0; jj < 8; jj++)
                    acc[ii][jj] = fmaf(a[ii], bb[jj], acc[ii][jj]);
        }
    }

    #pragma unroll
    for (int ii = 0; ii < 8; ii++) {
        int i = i0 + ty * 8 + ii;
        size_t base = ((size_t)b << 20) + (size_t)i * NMAT + j0 + tx * 8;
        *reinterpret_cast<float4*>(&Sout[base]) =
            make_float4(acc[ii][0], acc[ii][1], acc[ii][2], acc[ii][3]);
        *reinterpret_cast<float4*>(&Sout[base + 4]) =
            make_float4(acc[ii][4], acc[ii][5], acc[ii][6], acc[ii][7]);
        float e[8];
        #pragma unroll
        for (int jj = 0; jj < 8; jj++)
            e[jj] = __expf(5.f * fminf(fmaxf(acc[ii][jj], -3.f), 3.f));
        __half2 h0 = __floats2half2_rn(e[0], e[1]);
        __half2 h1 = __floats2half2_rn(e[2], e[3]);
        __half2 h2 = __floats2half2_rn(e[4], e[5]);
        __half2 h3 = __floats2half2_rn(e[6], e[7]);
        uint4 kq;
        kq.x = *reinterpret_cast<unsigned*>(&h0);
        kq.y = *reinterpret_cast<unsigned*>(&h1);
        kq.z = *reinterpret_cast<unsigned*>(&h2);
        kq.w = *reinterpret_cast<unsigned*>(&h3);
        *reinterpret_cast<uint4*>(&g_K[base]) = kq;
    }
}

// ---------------- grid barrier (128 blocks, all resident: 1 CTA/SM) ----------------
__device__ __forceinline__ void grid_barrier() {
    __syncthreads();
    if (threadIdx.x == 0) {
        __threadfence();
        unsigned gen = *reinterpret_cast<volatile unsigned*>(&g_bar_gen);
        if (atomicAdd(&g_bar_count, 1u) == GRID_SINK - 1) {
            g_bar_count = 0;
            __threadfence();
            atomicAdd(&g_bar_gen, 1u);
        } else {
            while (*reinterpret_cast<volatile unsigned*>(&g_bar_gen) == gen) {
                __nanosleep(32);
            }
        }
        __threadfence();
    }
    __syncthreads();
}

// ---------------- persistent Sinkhorn: 101 fused (row+col) passes over fp16 K ----------------
// Block = (batch b, slice r of 8), 128 rows/block, 8 rows/warp processed as 4 PAIRS:
//   both rows' 8 LDG.128 issued up front, two independent dot chains, ONE batched
//   5-level shfl phase for both dots, then re-convert raw half2 regs for col accumulate.
__global__ void __launch_bounds__(TPB_SINK, 1) sinkhorn_kernel(float* __restrict__ Pout) {
    const int b = blockIdx.x >> 3;
    const int r = blockIdx.x & 7;
    const int row0 = r * ROWS_PER_BLK;
    const int tid = threadIdx.x, w = tid >> 5, lane = tid & 31;

    extern __shared__ float sm[];
    float* v_s     = sm;            // 1024
    float* u_s     = sm + 1024;     // 128
    float* colpart = sm + 1152;     // 16 * 1024

    const __half* Kb = g_K + ((size_t)b << 20);

    ull vp[16];   // packed v pairs for owned columns {256k + 8*lane + m}
    ull ca[16];   // packed column accumulators

    for (int t = 0; t < ITERS; t++) {
        const int wb = t & 1;
        // ---- phase A: build v ----
        if (t == 0) {
            #pragma unroll
            for (int m = 0; m < 16; m++) vp[m] = packf2(1.0f, 1.0f);
        } else {
            const int rb = wb ^ 1;
            for (int c = tid; c < NMAT; c += TPB_SINK) {   // 2 cols/thread
                float s = 0.f;
                #pragma unroll
                for (int rr = 0; rr < NBLK_PER_B; rr++) s += g_part[rb][b][rr][c];
                v_s[c] = 1.0f / s;
            }
            __syncthreads();
            #pragma unroll
            for (int k = 0; k < 4; k++) {
                ulonglong2 va = *reinterpret_cast<const ulonglong2*>(&v_s[256*k + 8*lane]);
                ulonglong2 vb = *reinterpret_cast<const ulonglong2*>(&v_s[256*k + 8*lane + 4]);
                vp[4*k+0] = va.x;  vp[4*k+1] = va.y;
                vp[4*k+2] = vb.x;  vp[4*k+3] = vb.y;
            }
        }
        #pragma unroll
        for (int m = 0; m < 16; m++) ca[m] = 0ull;

        // ---- phase B: 4 row-pairs, fused matvec + col accumulate ----
        #pragma unroll 1
        for (int p = 0; p < 4; p++) {
            const int ilA = w + 32 * p;
            const int ilB = ilA + 16;
            const uint4* KrA = reinterpret_cast<const uint4*>(Kb + (size_t)(row0 + ilA) * NMAT);
            const uint4* KrB = reinterpret_cast<const uint4*>(Kb + (size_t)(row0 + ilB) * NMAT);
            // front-batched loads for BOTH rows (MLP 8)
            uint4 qA0 = KrA[lane], qA1 = KrA[32+lane], qA2 = KrA[64+lane], qA3 = KrA[96+lane];
            uint4 qB0 = KrB[lane], qB1 = KrB[32+lane], qB2 = KrB[64+lane], qB3 = KrB[96+lane];

            // two independent dot chains (transient conversions, no kf kept)
            ull a0 = 0ull, a1 = 0ull, b0 = 0ull, b1 = 0ull;
            {
                const uint4 qa[4] = {qA0, qA1, qA2, qA3};
                const uint4 qb[4] = {qB0, qB1, qB2, qB3};
                #pragma unroll
                for (int k = 0; k < 4; k++) {
                    ffma2(a0, h2f2(qa[k].x), vp[4*k+0]);
                    ffma2(b0, h2f2(qb[k].x), vp[4*k+0]);
                    ffma2(a1, h2f2(qa[k].y), vp[4*k+1]);
                    ffma2(b1, h2f2(qb[k].y), vp[4*k+1]);
                    ffma2(a0, h2f2(qa[k].z), vp[4*k+2]);
                    ffma2(b0, h2f2(qb[k].z), vp[4*k+2]);
                    ffma2(a1, h2f2(qa[k].w), vp[4*k+3]);
                    ffma2(b1, h2f2(qb[k].w), vp[4*k+3]);
                }
            }
            float2 fa0 = unpackf2(a0), fa1 = unpackf2(a1);
            float2 fb0 = unpackf2(b0), fb1 = unpackf2(b1);
            float dA = (fa0.x + fa0.y) + (fa1.x + fa1.y);
            float dB = (fb0.x + fb0.y) + (fb1.x + fb1.y);
            // ONE batched shuffle phase for both rows (pipelined levels)
            #pragma unroll
            for (int off = 16; off; off >>= 1) {
                dA += __shfl_xor_sync(0xffffffffu, dA, off);
                dB += __shfl_xor_sync(0xffffffffu, dB, off);
            }
            float uA = 1.0f / dA;
            float uB = 1.0f / dB;
            if (lane == 0) { u_s[ilA] = uA; u_s[ilB] = uB; }
            ull upA = packf2(uA, uA);
            ull upB = packf2(uB, uB);
            // re-convert raw regs, accumulate columns for both rows
            {
                const uint4 qa[4] = {qA0, qA1, qA2, qA3};
                const uint4 qb[4] = {qB0, qB1, qB2, qB3};
                #pragma unroll
                for (int k = 0; k < 4; k++) {
                    ffma2(ca[4*k+0], upA, h2f2(qa[k].x));
                    ffma2(ca[4*k+1], upA, h2f2(qa[k].y));
                    ffma2(ca[4*k+2], upA, h2f2(qa[k].z));
                    ffma2(ca[4*k+3], upA, h2f2(qa[k].w));
                    ffma2(ca[4*k+0], upB, h2f2(qb[k].x));
                    ffma2(ca[4*k+1], upB, h2f2(qb[k].y));
                    ffma2(ca[4*k+2], upB, h2f2(qb[k].z));
                    ffma2(ca[4*k+3], upB, h2f2(qb[k].w));
                }
            }
        }

        // ---- phase C: per-warp partials -> block partial -> global ----
        #pragma unroll
        for (int k = 0; k < 4; k++) {
            float2 p0 = unpackf2(ca[4*k+0]);
            float2 p1 = unpackf2(ca[4*k+1]);
            float2 p2 = unpackf2(ca[4*k+2]);
            float2 p3 = unpackf2(ca[4*k+3]);
            *reinterpret_cast<float4*>(&colpart[w*1024 + 256*k + 8*lane]) =
                make_float4(p0.x, p0.y, p1.x, p1.y);
            *reinterpret_cast<float4*>(&colpart[w*1024 + 256*k + 8*lane + 4]) =
                make_float4(p2.x, p2.y, p3.x, p3.y);
        }
        __syncthreads();
        for (int c = tid; c < NMAT; c += TPB_SINK) {
            float s = 0.f;
            #pragma unroll
            for (int ww = 0; ww < 16; ww++) s += colpart[ww * 1024 + c];
            g_part[wb][b][r][c] = s;
        }
        grid_barrier();
    }

    // ---- final: v from last partials (buffer (ITERS-1)&1 == 0), P_out = u*K*v ----
    {
        const int fb = (ITERS - 1) & 1;
        for (int c = tid; c < NMAT; c += TPB_SINK) {
            float s = 0.f;
            #pragma unroll
            for (int rr = 0; rr < NBLK_PER_B; rr++) s += g_part[fb][b][rr][c];
            v_s[c] = 1.0f / s;
        }
        __syncthreads();
        float vr[32];
        #pragma unroll
        for (int k = 0; k < 4; k++) {
            float4 va = *reinterpret_cast<const float4*>(&v_s[256*k + 8*lane]);
            float4 vb = *reinterpret_cast<const float4*>(&v_s[256*k + 8*lane + 4]);
            vr[8*k+0] = va.x; vr[8*k+1] = va.y; vr[8*k+2] = va.z; vr[8*k+3] = va.w;
            vr[8*k+4] = vb.x; vr[8*k+5] = vb.y; vr[8*k+6] = vb.z; vr[8*k+7] = vb.w;
        }
        for (int il = w; il < ROWS_PER_BLK; il += 16) {
            const int i = row0 + il;
            const uint4* Krow = reinterpret_cast<const uint4*>(Kb + (size_t)i * NMAT);
            float u = u_s[il];
            float* Orow = Pout + ((size_t)b << 20) + (size_t)i * NMAT;
            #pragma unroll
            for (int k = 0; k < 4; k++) {
                uint4 q = Krow[32*k + lane];
                float2 f0 = __half22float2(*reinterpret_cast<__half2*>(&q.x));
                float2 f1 = __half22float2(*reinterpret_cast<__half2*>(&q.y));
                float2 f2 = __half22float2(*reinterpret_cast<__half2*>(&q.z));
                float2 f3 = __half22float2(*reinterpret_cast<__half2*>(&q.w));
                *reinterpret_cast<float4*>(&Orow[256*k + 8*lane]) =
                    make_float4(u*f0.x*vr[8*k+0], u*f0.y*vr[8*k+1],
                                u*f1.x*vr[8*k+2], u*f1.y*vr[8*k+3]);
                *reinterpret_cast<float4*>(&Orow[256*k + 8*lane + 4]) =
                    make_float4(u*f2.x*vr[8*k+4], u*f2.y*vr[8*k+5],
                                u*f3.x*vr[8*k+6], u*f3.y*vr[8*k+7]);
            }
        }
    }
}

// ---------------- launch ----------------
extern "C" void kernel_launch(void* const* d_in, const int* in_sizes, int n_in,
                              void* d_out, int out_size) {
    const float* fA = (const float*)d_in[0];
    const float* fB = (const float*)d_in[1];
    float* out  = (float*)d_out;
    float* Pout = out;                                        // P_out: [16,1024,1024]
    float* Sout = out + (size_t)BATCH * NMAT * NMAT;          // Sij:   [16,1024,1024]

    norm_kernel<<<2048, 256>>>(fA, 0);
    norm_kernel<<<2048, 256>>>(fB, 1);

    dim3 ggrid(8, 8, BATCH);
    gemm_expk_kernel<<<ggrid, 256>>>(Sout);

    const int smem_bytes = (1024 + 128 + 16 * 1024) * sizeof(float);   // 70144
    cudaFuncSetAttribute(sinkhorn_kernel,
                         cudaFuncAttributeMaxDynamicSharedMemorySize, smem_bytes);
    sinkhorn_kernel<<<GRID_SINK, TPB_SINK, smem_bytes>>>(Pout);
}

// round 8
// speedup vs baseline: 1.5407x; 1.2114x over previous
#include <cuda_runtime.h>
#include <cuda_fp16.h>

#define BATCH 16
#define NMAT  1024
#define DDIM  256
#define ITERS 101          // 100 scan steps + 1 final sinkhorn_step
#define NBLK_PER_B 9
#define GRID_SINK (BATCH * NBLK_PER_B)   // 144 blocks, all resident on 148 SMs
#define TPB_SINK  512                    // 16 warps

typedef unsigned long long ull;

// ---------------- f32x2 helpers (FFMA2 — only reachable via PTX) ----------------
__device__ __forceinline__ void ffma2(ull& d, ull a, ull b) {
    asm("fma.rn.f32x2 %0, %1, %2, %3;" : "=l"(d) : "l"(a), "l"(b), "l"(d));
}
__device__ __forceinline__ ull packf2(float lo, float hi) {
    ull r; asm("mov.b64 %0, {%1, %2};" : "=l"(r) : "f"(lo), "f"(hi)); return r;
}
__device__ __forceinline__ float2 unpackf2(ull v) {
    float lo, hi; asm("mov.b64 {%0, %1}, %2;" : "=f"(lo), "=f"(hi) : "l"(v));
    return make_float2(lo, hi);
}

// ---------------- device scratch (no allocations allowed) ----------------
__device__ float  g_nA[BATCH * NMAT * DDIM];                 // 16.8 MB
__device__ float  g_nB[BATCH * NMAT * DDIM];                 // 16.8 MB
__device__ __half g_K[(size_t)BATCH * NMAT * NMAT];          // 33.5 MB (L2-resident)
__device__ float  g_part[2][BATCH][NBLK_PER_B][NMAT];        // double-buffered col partials

// per-batch monotonic produced-counter + done-counter, each on its own 128B line
struct __align__(128) BatchSync { unsigned produced; unsigned done; unsigned pad[30]; };
__device__ BatchSync g_sync[BATCH];   // zero-initialized; reset in-kernel for graph replay

// ---------------- l2 normalize: warp per row (256 elems) ----------------
__global__ void norm_kernel(const float* __restrict__ in, int which) {
    int w = threadIdx.x >> 5, lane = threadIdx.x & 31;
    int row = blockIdx.x * 8 + w;                      // 2048 blocks * 8 = 16384 rows
    const float4* src = reinterpret_cast<const float4*>(in) + (size_t)row * 64;
    float4 x0 = src[lane];
    float4 x1 = src[lane + 32];
    float s = x0.x * x0.x + x0.y * x0.y + x0.z * x0.z + x0.w * x0.w
            + x1.x * x1.x + x1.y * x1.y + x1.z * x1.z + x1.w * x1.w;
    #pragma unroll
    for (int off = 16; off; off >>= 1) s += __shfl_xor_sync(0xffffffffu, s, off);
    float r = rsqrtf(fmaxf(s, 1e-12f));
    float* dst = (which ? g_nB : g_nA) + (size_t)row * 256;
    reinterpret_cast<float4*>(dst)[lane]      = make_float4(x0.x*r, x0.y*r, x0.z*r, x0.w*r);
    reinterpret_cast<float4*>(dst)[lane + 32] = make_float4(x1.x*r, x1.y*r, x1.z*r, x1.w*r);
}

// ---------------- GEMM (plain FFMA): S = nA*nB^T, K = fp16(exp(5*clamp(S))) ----
// grid (8, 8, 16), block 256, 128x128 tile, 8x8 per thread, BK=32
__global__ void __launch_bounds__(256) gemm_expk_kernel(float* __restrict__ Sout) {
    __shared__ float As[32 * 128];   // [k][i]
    __shared__ float Bs[32 * 128];   // [k][j]
    const int b  = blockIdx.z;
    const int i0 = blockIdx.y * 128;
    const int j0 = blockIdx.x * 128;
    const float* Ag = g_nA + (size_t)b * NMAT * DDIM;
    const float* Bg = g_nB + (size_t)b * NMAT * DDIM;
    const int tid = threadIdx.x;
    const int tx = tid & 15, ty = tid >> 4;
    const int lr = tid >> 3;
    const int lc = tid & 7;

    float acc[8][8];
    #pragma unroll
    for (int i = 0; i < 8; i++)
        #pragma unroll
        for (int j = 0; j < 8; j++) acc[i][j] = 0.f;

    for (int kc = 0; kc < 8; kc++) {
        __syncthreads();
        #pragma unroll
        for (int g = 0; g < 4; g++) {
            int row = lr + 32 * g;
            float4 av = *reinterpret_cast<const float4*>(
                &Ag[(size_t)(i0 + row) * DDIM + kc * 32 + lc * 4]);
            As[(lc * 4 + 0) * 128 + row] = av.x;
            As[(lc * 4 + 1) * 128 + row] = av.y;
            As[(lc * 4 + 2) * 128 + row] = av.z;
            As[(lc * 4 + 3) * 128 + row] = av.w;
            float4 bv = *reinterpret_cast<const float4*>(
                &Bg[(size_t)(j0 + row) * DDIM + kc * 32 + lc * 4]);
            Bs[(lc * 4 + 0) * 128 + row] = bv.x;
            Bs[(lc * 4 + 1) * 128 + row] = bv.y;
            Bs[(lc * 4 + 2) * 128 + row] = bv.z;
            Bs[(lc * 4 + 3) * 128 + row] = bv.w;
        }
        __syncthreads();
        #pragma unroll
        for (int k = 0; k < 32; k++) {
            float4 a0 = *reinterpret_cast<const float4*>(&As[k * 128 + ty * 8]);
            float4 a1 = *reinterpret_cast<const float4*>(&As[k * 128 + ty * 8 + 4]);
            float4 b0 = *reinterpret_cast<const float4*>(&Bs[k * 128 + tx * 8]);
            float4 b1 = *reinterpret_cast<const float4*>(&Bs[k * 128 + tx * 8 + 4]);
            float a[8] = {a0.x, a0.y, a0.z, a0.w, a1.x, a1.y, a1.z, a1.w};
            float bb[8] = {b0.x, b0.y, b0.z, b0.w, b1.x, b1.y, b1.z, b1.w};
            #pragma unroll
            for (int ii = 0; ii < 8; ii++)
                #pragma unroll
                for (int jj = 0; jj < 8; jj++)
                    acc[ii][jj] = fmaf(a[ii], bb[jj], acc[ii][jj]);
        }
    }

    #pragma unroll
    for (int ii = 0; ii < 8; ii++) {
        int i = i0 + ty * 8 + ii;
        size_t base = ((size_t)b << 20) + (size_t)i * NMAT + j0 + tx * 8;
        *reinterpret_cast<float4*>(&Sout[base]) =
            make_float4(acc[ii][0], acc[ii][1], acc[ii][2], acc[ii][3]);
        *reinterpret_cast<float4*>(&Sout[base + 4]) =
            make_float4(acc[ii][4], acc[ii][5], acc[ii][6], acc[ii][7]);
        float e[8];
        #pragma unroll
        for (int jj = 0; jj < 8; jj++)
            e[jj] = __expf(5.f * fminf(fmaxf(acc[ii][jj], -3.f), 3.f));
        __half2 h0 = __floats2half2_rn(e[0], e[1]);
        __half2 h1 = __floats2half2_rn(e[2], e[3]);
        __half2 h2 = __floats2half2_rn(e[4], e[5]);
        __half2 h3 = __floats2half2_rn(e[6], e[7]);
        uint4 kq;
        kq.x = *reinterpret_cast<unsigned*>(&h0);
        kq.y = *reinterpret_cast<unsigned*>(&h1);
        kq.z = *reinterpret_cast<unsigned*>(&h2);
        kq.w = *reinterpret_cast<unsigned*>(&h3);
        *reinterpret_cast<uint4*>(&g_K[base]) = kq;
    }
}

// ---------------- per-batch producer/consumer sync ----------------
// Producer (end of iteration): all threads stored partials; __syncthreads();
// tid0: __threadfence() (release) then atomicAdd(produced, 1).
// Consumer (top of iteration t): tid0 spins until produced >= 9*t, __threadfence()
// (acquire), then __syncthreads() releases the block.
__device__ __forceinline__ void wait_produced(int b, unsigned need) {
    if (threadIdx.x == 0) {
        while (*reinterpret_cast<volatile unsigned*>(&g_sync[b].produced) < need) {
            __nanosleep(32);
        }
        __threadfence();
    }
    __syncthreads();
}

// ---------------- persistent Sinkhorn: 101 fused (row+col) passes over fp16 K ----------------
// Block = (batch b, slice r of 9). Warp processes whole rows; lane owns cols {256k + 8*lane + m}.
// EXACT R2 phase-B structure (known best); only the sync mechanism changed.
__global__ void __launch_bounds__(TPB_SINK, 1) sinkhorn_kernel(float* __restrict__ Pout) {
    const int b = blockIdx.x / NBLK_PER_B;
    const int r = blockIdx.x % NBLK_PER_B;
    const int row0  = r * 114;
    const int nrows = (r == 8) ? 112 : 114;          // 8*114 + 112 = 1024
    const int tid = threadIdx.x, w = tid >> 5, lane = tid & 31;

    extern __shared__ float sm[];
    float* v_s     = sm;            // 1024
    float* u_s     = sm + 1024;     // 128 (114 used)
    float* colpart = sm + 1152;     // 16 * 1024

    const __half* Kb = g_K + ((size_t)b << 20);

    ull vp[16];   // packed v pairs for owned columns
    ull ca[16];   // packed column accumulators

    for (int t = 0; t < ITERS; t++) {
        const int wb = t & 1;        // buffer written this iteration
        // ---- phase A: wait for peers' partials from iter t-1, build v ----
        if (t == 0) {
            #pragma unroll
            for (int m = 0; m < 16; m++) vp[m] = packf2(1.0f, 1.0f);
        } else {
            wait_produced(b, (unsigned)(NBLK_PER_B * t));
            const int rb = wb ^ 1;   // buffer written by iteration t-1
            for (int c = tid; c < NMAT; c += TPB_SINK) {
                float s = 0.f;
                #pragma unroll
                for (int rr = 0; rr < NBLK_PER_B; rr++) s += g_part[rb][b][rr][c];
                v_s[c] = 1.0f / s;
            }
            __syncthreads();
            #pragma unroll
            for (int k = 0; k < 4; k++) {
                ulonglong2 va = *reinterpret_cast<const ulonglong2*>(&v_s[256*k + 8*lane]);
                ulonglong2 vb = *reinterpret_cast<const ulonglong2*>(&v_s[256*k + 8*lane + 4]);
                vp[4*k+0] = va.x;  vp[4*k+1] = va.y;
                vp[4*k+2] = vb.x;  vp[4*k+3] = vb.y;
            }
        }
        #pragma unroll
        for (int m = 0; m < 16; m++) ca[m] = 0ull;

        // ---- phase B: fused row matvec + col accumulate (one K pass) ----
        for (int il = w; il < nrows; il += 16) {
            const int i = row0 + il;
            const uint4* Krow = reinterpret_cast<const uint4*>(Kb + (size_t)i * NMAT);
            ull kf[16];
            ull d0 = 0ull, d1 = 0ull;
            #pragma unroll
            for (int k = 0; k < 4; k++) {
                uint4 q = Krow[32*k + lane];
                float2 f0 = __half22float2(*reinterpret_cast<__half2*>(&q.x));
                float2 f1 = __half22float2(*reinterpret_cast<__half2*>(&q.y));
                float2 f2 = __half22float2(*reinterpret_cast<__half2*>(&q.z));
                float2 f3 = __half22float2(*reinterpret_cast<__half2*>(&q.w));
                kf[4*k+0] = packf2(f0.x, f0.y);
                kf[4*k+1] = packf2(f1.x, f1.y);
                kf[4*k+2] = packf2(f2.x, f2.y);
                kf[4*k+3] = packf2(f3.x, f3.y);
                ffma2(d0, kf[4*k+0], vp[4*k+0]);
                ffma2(d1, kf[4*k+1], vp[4*k+1]);
                ffma2(d0, kf[4*k+2], vp[4*k+2]);
                ffma2(d1, kf[4*k+3], vp[4*k+3]);
            }
            float2 dd0 = unpackf2(d0), dd1 = unpackf2(d1);
            float dot = (dd0.x + dd0.y) + (dd1.x + dd1.y);
            #pragma unroll
            for (int off = 16; off; off >>= 1) dot += __shfl_xor_sync(0xffffffffu, dot, off);
            float u = 1.0f / dot;
            if (lane == 0) u_s[il] = u;
            ull up = packf2(u, u);
            #pragma unroll
            for (int m = 0; m < 16; m++) ffma2(ca[m], up, kf[m]);
        }

        // ---- phase C: per-warp partials -> block partial -> global, then produce ----
        #pragma unroll
        for (int k = 0; k < 4; k++) {
            float2 p0 = unpackf2(ca[4*k+0]);
            float2 p1 = unpackf2(ca[4*k+1]);
            float2 p2 = unpackf2(ca[4*k+2]);
            float2 p3 = unpackf2(ca[4*k+3]);
            *reinterpret_cast<float4*>(&colpart[w*1024 + 256*k + 8*lane]) =
                make_float4(p0.x, p0.y, p1.x, p1.y);
            *reinterpret_cast<float4*>(&colpart[w*1024 + 256*k + 8*lane + 4]) =
                make_float4(p2.x, p2.y, p3.x, p3.y);
        }
        __syncthreads();
        for (int c = tid; c < NMAT; c += TPB_SINK) {
            float s = 0.f;
            #pragma unroll
            for (int ww = 0; ww < 16; ww++) s += colpart[ww * 1024 + c];
            g_part[wb][b][r][c] = s;
        }
        __syncthreads();                  // all partial stores done block-wide
        if (tid == 0) {
            __threadfence();              // release
            atomicAdd(&g_sync[b].produced, 1u);
        }
    }

    // ---- final: wait all ITERS produced, v from buffer (ITERS-1)&1, P_out = u*K*v ----
    {
        wait_produced(b, (unsigned)(NBLK_PER_B * ITERS));
        const int fb = (ITERS - 1) & 1;
        for (int c = tid; c < NMAT; c += TPB_SINK) {
            float s = 0.f;
            #pragma unroll
            for (int rr = 0; rr < NBLK_PER_B; rr++) s += g_part[fb][b][rr][c];
            v_s[c] = 1.0f / s;
        }
        __syncthreads();
        float vr[32];
        #pragma unroll
        for (int k = 0; k < 4; k++) {
            float4 va = *reinterpret_cast<const float4*>(&v_s[256*k + 8*lane]);
            float4 vb = *reinterpret_cast<const float4*>(&v_s[256*k + 8*lane + 4]);
            vr[8*k+0] = va.x; vr[8*k+1] = va.y; vr[8*k+2] = va.z; vr[8*k+3] = va.w;
            vr[8*k+4] = vb.x; vr[8*k+5] = vb.y; vr[8*k+6] = vb.z; vr[8*k+7] = vb.w;
        }
        for (int il = w; il < nrows; il += 16) {
            const int i = row0 + il;
            const uint4* Krow = reinterpret_cast<const uint4*>(Kb + (size_t)i * NMAT);
            float u = u_s[il];
            float* Orow = Pout + ((size_t)b << 20) + (size_t)i * NMAT;
            #pragma unroll
            for (int k = 0; k < 4; k++) {
                uint4 q = Krow[32*k + lane];
                float2 f0 = __half22float2(*reinterpret_cast<__half2*>(&q.x));
                float2 f1 = __half22float2(*reinterpret_cast<__half2*>(&q.y));
                float2 f2 = __half22float2(*reinterpret_cast<__half2*>(&q.z));
                float2 f3 = __half22float2(*reinterpret_cast<__half2*>(&q.w));
                *reinterpret_cast<float4*>(&Orow[256*k + 8*lane]) =
                    make_float4(u*f0.x*vr[8*k+0], u*f0.y*vr[8*k+1],
                                u*f1.x*vr[8*k+2], u*f1.y*vr[8*k+3]);
                *reinterpret_cast<float4*>(&Orow[256*k + 8*lane + 4]) =
                    make_float4(u*f2.x*vr[8*k+4], u*f2.y*vr[8*k+5],
                                u*f3.x*vr[8*k+6], u*f3.y*vr[8*k+7]);
            }
        }
    }

    // ---- reset counters for next graph replay (last block of the batch does it) ----
    __syncthreads();
    if (threadIdx.x == 0) {
        __threadfence();
        unsigned old = atomicAdd(&g_sync[b].done, 1u);
        if (old == NBLK_PER_B - 1) {
            g_sync[b].produced = 0;
            g_sync[b].done = 0;
            __threadfence();
        }
    }
}

// ---------------- launch ----------------
extern "C" void kernel_launch(void* const* d_in, const int* in_sizes, int n_in,
                              void* d_out, int out_size) {
    const float* fA = (const float*)d_in[0];
    const float* fB = (const float*)d_in[1];
    float* out  = (float*)d_out;
    float* Pout = out;                                        // P_out: [16,1024,1024]
    float* Sout = out + (size_t)BATCH * NMAT * NMAT;          // Sij:   [16,1024,1024]

    norm_kernel<<<2048, 256>>>(fA, 0);
    norm_kernel<<<2048, 256>>>(fB, 1);

    dim3 ggrid(8, 8, BATCH);
    gemm_expk_kernel<<<ggrid, 256>>>(Sout);

    const int smem_bytes = (1024 + 128 + 16 * 1024) * sizeof(float);   // 70144
    cudaFuncSetAttribute(sinkhorn_kernel,
                         cudaFuncAttributeMaxDynamicSharedMemorySize, smem_bytes);
    sinkhorn_kernel<<<GRID_SINK, TPB_SINK, smem_bytes>>>(Pout);
}